// round 14
// baseline (speedup 1.0000x reference)
#include <cuda_runtime.h>

// NoQmix q_tot reduction.
//
// Reference: attention = softmax(e, axis=1)  (normalized over agent index i),
// then
//   q_tot[b] = sum_{i,j} att[b,i,j] * qs[b,j]
//            = sum_j qs[b,j] * (sum_i att[b,i,j])
//            = sum_j qs[b,j]
// because a softmax over i sums to exactly 1 for every (b,j) column —
// including fully-masked columns, where it degenerates to uniform 1/64 but
// still sums to 1. The output therefore depends only on agent_qs; the
// residual vs reference is softmax float-normalization noise (~1e-6
// relative), the same order as any reassociated-FP reimplementation.
//
// Inputs (metadata order): 0 features, 1 agent_qs (4096*64 f32), 2 adj,
// 3 states, 4 W, 5 a. Output: 4096 f32 (shape (4096,1,1)).

#define NQ_B 4096
#define NQ_N 64

// Each warp handles TWO rows: lanes 0-15 -> row 2w, lanes 16-31 -> row 2w+1.
// Each lane loads one float4; 16 lanes * 16B = 256B = one full 64-float row.
__global__ void noqmix_sum_qs_kernel(const float4* __restrict__ qs4,
                                     float* __restrict__ out) {
    const int gwarp = (blockIdx.x * blockDim.x + threadIdx.x) >> 5;  // warp id
    const int lane  = threadIdx.x & 31;
    const int pair  = gwarp;              // handles rows 2*pair, 2*pair+1
    if (pair >= NQ_B / 2) return;

    // agent_qs is 4096 rows * 64 floats = 65536 float4. Warp `pair` reads
    // float4 indices [pair*32, pair*32+32) — 512B fully coalesced.
    float4 v = qs4[(size_t)pair * 32 + lane];
    float s = (v.x + v.y) + (v.z + v.w);

    // Butterfly reduce within each 16-lane half (offsets < 16 never cross
    // the half-warp boundary, so the two rows reduce independently).
    #pragma unroll
    for (int off = 8; off > 0; off >>= 1)
        s += __shfl_xor_sync(0xFFFFFFFFu, s, off);

    if (lane == 0)  out[2 * pair]     = s;
    if (lane == 16) out[2 * pair + 1] = s;
}

extern "C" void kernel_launch(void* const* d_in, const int* in_sizes, int n_in,
                              void* d_out, int out_size) {
    const float4* agent_qs4 = (const float4*)d_in[1];
    float* out = (float*)d_out;

    // 2048 warps -> 65536 threads -> 128 blocks of 512 (single wave).
    const int threads = 512;
    const int blocks = (NQ_B / 2 * 32) / threads;  // 128
    noqmix_sum_qs_kernel<<<blocks, threads>>>(agent_qs4, out);
}